// round 1
// baseline (speedup 1.0000x reference)
#include <cuda_runtime.h>
#include <cuda_bf16.h>

// ModulatedConv2d: B=8, Cin=512, Cout=512, K=3, S=512, H=W=64
// out = demod-scaled conv of (s-modulated x) with shared weight; plus s5 output.

#define B_      8
#define CIN     512
#define COUT    512
#define S_DIM   512
#define HW      64
#define LIN_SCALE   0.044194173824159216f   // 1/sqrt(512)
#define CONV_SCALE  0.014731391274719739f   // 1/sqrt(512*9)
#define EPS_        1e-8f

__device__ float g_s[B_ * CIN];       // s[b][ci]
__device__ float g_scale[B_ * COUT];  // conv_scale * demod[b][co]

// ---------------------------------------------------------------------------
// Kernel 1: s[b,ci] = sum_j style[b,j]*mod_weight[ci,j]*lin_scale + mod_bias[ci]
// grid = B_, block = 512 (one thread per ci). Also writes s5 output tail.
// ---------------------------------------------------------------------------
__global__ void style_kernel(const float* __restrict__ style,
                             const float* __restrict__ modw,
                             const float* __restrict__ modb,
                             float* __restrict__ out_s5) {
    __shared__ float st[S_DIM];
    int b = blockIdx.x;
    int ci = threadIdx.x;
    st[ci] = style[b * S_DIM + ci];
    __syncthreads();

    const float* mrow = modw + (long long)ci * S_DIM;
    float acc = 0.f;
#pragma unroll 8
    for (int j = 0; j < S_DIM; ++j) {
        acc = fmaf(st[j], mrow[j], acc);
    }
    float s = acc * LIN_SCALE + modb[ci];
    g_s[b * CIN + ci] = s;
    out_s5[b * CIN + ci] = s;   // s5 flattened: (B,1,Cin,1,1) -> B*Cin
}

// ---------------------------------------------------------------------------
// Kernel 2: per-(b,co) demod scale.
// scale = conv_scale * rsqrt( conv_scale^2 * sum_ci s[b,ci]^2 * sum_k W[co,ci,k]^2 + eps )
// grid = B_*COUT blocks, 128 threads each.
// ---------------------------------------------------------------------------
__global__ void demod_kernel(const float* __restrict__ weight) {
    int bc = blockIdx.x;
    int b = bc >> 9;
    int co = bc & 511;
    int tid = threadIdx.x;

    float acc = 0.f;
    for (int ci = tid; ci < CIN; ci += 128) {
        const float* wp = weight + ((long long)co * CIN + ci) * 9;
        float wsq = 0.f;
#pragma unroll
        for (int k = 0; k < 9; ++k) wsq = fmaf(wp[k], wp[k], wsq);
        float s = g_s[b * CIN + ci];
        acc = fmaf(wsq, s * s, acc);
    }
    // warp reduce
#pragma unroll
    for (int off = 16; off > 0; off >>= 1)
        acc += __shfl_xor_sync(0xffffffffu, acc, off);

    __shared__ float part[4];
    int lane = tid & 31, wid = tid >> 5;
    if (lane == 0) part[wid] = acc;
    __syncthreads();
    if (tid == 0) {
        float tot = part[0] + part[1] + part[2] + part[3];
        g_scale[bc] = CONV_SCALE * rsqrtf(CONV_SCALE * CONV_SCALE * tot + EPS_);
    }
}

// ---------------------------------------------------------------------------
// Kernel 3: the conv. Block computes a 32x32 spatial tile x 8 output channels
// for one batch. 256 threads (16x16), each thread owns 2x2 outputs x 8 co.
// Inner loop over Cin in steps of 4, x patch (with s folded in) in smem.
// ---------------------------------------------------------------------------
#define CI_STEP 4
#define CO_TILE 8

__global__ __launch_bounds__(256)
void conv_kernel(const float* __restrict__ x,
                 const float* __restrict__ weight,
                 float* __restrict__ out) {
    __shared__ float xs[CI_STEP][34][36];       // 34x34 patch, padded stride
    __shared__ float ws[CI_STEP][CO_TILE][9];

    const int b   = blockIdx.z;
    const int cob = blockIdx.x * CO_TILE;
    const int h0  = (blockIdx.y >> 1) * 32;
    const int w0  = (blockIdx.y & 1) * 32;
    const int tid = threadIdx.x;
    const int tx  = tid & 15;
    const int ty  = tid >> 4;

    float acc[CO_TILE][4];
#pragma unroll
    for (int c = 0; c < CO_TILE; ++c)
#pragma unroll
        for (int p = 0; p < 4; ++p) acc[c][p] = 0.f;

    const float* sptr = &g_s[b * CIN];

    for (int cib = 0; cib < CIN; cib += CI_STEP) {
        __syncthreads();   // protect smem from previous iteration's readers

        // load x patch (s-modulated): CI_STEP * 34 * 34 = 4624 elements
        for (int i = tid; i < CI_STEP * 34 * 34; i += 256) {
            int ci = i / (34 * 34);
            int r  = i - ci * (34 * 34);
            int py = r / 34;
            int px = r - py * 34;
            int gy = h0 - 1 + py;
            int gx = w0 - 1 + px;
            int cig = cib + ci;
            float v = 0.f;
            if ((unsigned)gy < 64u && (unsigned)gx < 64u)
                v = x[((((long long)b * CIN + cig) * HW) + gy) * HW + gx];
            xs[ci][py][px] = v * __ldg(&sptr[cig]);
        }
        // load weights: CI_STEP * CO_TILE * 9 = 288 elements
        for (int i = tid; i < CI_STEP * CO_TILE * 9; i += 256) {
            int ci = i / (CO_TILE * 9);
            int r  = i - ci * (CO_TILE * 9);
            int co = r / 9;
            int k  = r - co * 9;
            ws[ci][co][k] = weight[(((long long)(cob + co) * CIN) + cib + ci) * 9 + k];
        }
        __syncthreads();

#pragma unroll
        for (int ci = 0; ci < CI_STEP; ++ci) {
            // 4x4 input window covering this thread's 2x2 outputs
            float xr[4][4];
#pragma unroll
            for (int i = 0; i < 4; ++i)
#pragma unroll
                for (int j = 0; j < 4; ++j)
                    xr[i][j] = xs[ci][2 * ty + i][2 * tx + j];

#pragma unroll
            for (int co = 0; co < CO_TILE; ++co) {
                float w[9];
#pragma unroll
                for (int k = 0; k < 9; ++k) w[k] = ws[ci][co][k];
#pragma unroll
                for (int dy = 0; dy < 2; ++dy)
#pragma unroll
                    for (int dx = 0; dx < 2; ++dx) {
                        float a = acc[co][dy * 2 + dx];
#pragma unroll
                        for (int kh = 0; kh < 3; ++kh)
#pragma unroll
                            for (int kw = 0; kw < 3; ++kw)
                                a = fmaf(w[kh * 3 + kw], xr[dy + kh][dx + kw], a);
                        acc[co][dy * 2 + dx] = a;
                    }
            }
        }
    }

    // epilogue: scale by conv_scale * demod and store
#pragma unroll
    for (int co = 0; co < CO_TILE; ++co) {
        float sc = g_scale[b * COUT + cob + co];
        long long base = (((long long)b * COUT + cob + co) * HW);
#pragma unroll
        for (int dy = 0; dy < 2; ++dy) {
            int py = h0 + 2 * ty + dy;
#pragma unroll
            for (int dx = 0; dx < 2; ++dx) {
                int px = w0 + 2 * tx + dx;
                out[(base + py) * HW + px] = acc[co][dy * 2 + dx] * sc;
            }
        }
    }
}

// ---------------------------------------------------------------------------
extern "C" void kernel_launch(void* const* d_in, const int* in_sizes, int n_in,
                              void* d_out, int out_size) {
    const float* x      = (const float*)d_in[0];
    const float* style  = (const float*)d_in[1];
    const float* weight = (const float*)d_in[2];
    const float* modw   = (const float*)d_in[3];
    const float* modb   = (const float*)d_in[4];
    float* out = (float*)d_out;

    // s5 output sits after the conv output in the flattened output buffer
    float* out_s5 = out + (long long)B_ * COUT * HW * HW;

    style_kernel<<<B_, S_DIM>>>(style, modw, modb, out_s5);
    demod_kernel<<<B_ * COUT, 128>>>(weight);

    dim3 grid(COUT / CO_TILE, 4, B_);   // 64 co-tiles x 4 spatial tiles x 8 batches
    conv_kernel<<<grid, 256>>>(x, weight, out);
}

// round 3
// speedup vs baseline: 4.8065x; 4.8065x over previous
#include <cuda_runtime.h>
#include <cstdint>

// ModulatedConv2d B=8, Cin=Cout=512, K=3, H=W=64
// tf32 mma.sync implicit GEMM (tcgen05 unavailable: harness PTX target is compute_103).

#define B_      8
#define CIN     512
#define COUT    512
#define HW2     4096
#define WPAD    66          // padded image width (64 + 2 halo)
#define MPLANE  4224        // 64 rows * 66
#define LIN_SCALE   0.044194173824159216f   // 1/sqrt(512)
#define CONV_SCALE  0.014731391274719739f   // 1/sqrt(512*9)
#define EPS_        1e-8f

// ---------------- device scratch ----------------
__device__ float g_s[B_ * CIN];
__device__ float g_scale[B_ * COUT];
__device__ float g_xt[(size_t)B_ * MPLANE * CIN];   // modulated, transposed, width-padded, tf32
__device__ float g_wt[9ull * COUT * CIN];           // [tap][co][ci], tf32

// ---------------- helpers ----------------
__device__ __forceinline__ uint32_t smem_u32(const void* p) {
    uint32_t a;
    asm("{ .reg .u64 t; cvta.to.shared.u64 t, %1; cvt.u32.u64 %0, t; }" : "=r"(a) : "l"(p));
    return a;
}
__device__ __forceinline__ uint32_t tf32r(float f) {
    uint32_t u;
    asm("cvt.rn.tf32.f32 %0, %1;" : "=r"(u) : "f"(f));
    return u;
}
__device__ __forceinline__ void cp16(uint32_t dst, const void* src, int srcsize) {
    asm volatile("cp.async.ca.shared.global [%0], [%1], 16, %2;"
                 :: "r"(dst), "l"(src), "r"(srcsize) : "memory");
}
#define CP_COMMIT() asm volatile("cp.async.commit_group;" ::: "memory")
#define CP_WAIT(n)  asm volatile("cp.async.wait_group %0;" :: "n"(n) : "memory")

__device__ __forceinline__ void mma_tf32(float* d, const uint32_t* a, const uint32_t* b) {
    asm volatile(
        "mma.sync.aligned.m16n8k8.row.col.f32.tf32.tf32.f32 "
        "{%0,%1,%2,%3}, {%4,%5,%6,%7}, {%8,%9}, {%0,%1,%2,%3};"
        : "+f"(d[0]), "+f"(d[1]), "+f"(d[2]), "+f"(d[3])
        : "r"(a[0]), "r"(a[1]), "r"(a[2]), "r"(a[3]), "r"(b[0]), "r"(b[1]));
}

// ---------------- kernel 1: style modulation ----------------
__global__ void style_kernel(const float* __restrict__ style,
                             const float* __restrict__ modw,
                             const float* __restrict__ modb,
                             float* __restrict__ out_s5) {
    __shared__ float st[512];
    int b = blockIdx.x, ci = threadIdx.x;
    st[ci] = style[b * 512 + ci];
    __syncthreads();
    const float4* mrow = (const float4*)(modw + (size_t)ci * 512);
    const float4* s4 = (const float4*)st;
    float a0 = 0.f, a1 = 0.f, a2 = 0.f, a3 = 0.f;
#pragma unroll 8
    for (int j = 0; j < 128; ++j) {
        float4 m = mrow[j];
        float4 s = s4[j];
        a0 = fmaf(s.x, m.x, a0);
        a1 = fmaf(s.y, m.y, a1);
        a2 = fmaf(s.z, m.z, a2);
        a3 = fmaf(s.w, m.w, a3);
    }
    float s = (a0 + a1 + a2 + a3) * LIN_SCALE + modb[ci];
    g_s[b * 512 + ci] = s;
    out_s5[b * 512 + ci] = s;
}

// ---------------- kernel 2: demod scales ----------------
__global__ void demod_kernel(const float* __restrict__ weight) {
    int bc = blockIdx.x;
    int b = bc >> 9, co = bc & 511;
    int tid = threadIdx.x;
    float acc = 0.f;
    for (int ci = tid; ci < CIN; ci += 128) {
        const float* wp = weight + ((size_t)co * CIN + ci) * 9;
        float wsq = 0.f;
#pragma unroll
        for (int k = 0; k < 9; ++k) wsq = fmaf(wp[k], wp[k], wsq);
        float s = g_s[b * CIN + ci];
        acc = fmaf(wsq, s * s, acc);
    }
#pragma unroll
    for (int off = 16; off > 0; off >>= 1) acc += __shfl_xor_sync(0xffffffffu, acc, off);
    __shared__ float part[4];
    int lane = tid & 31, wid = tid >> 5;
    if (lane == 0) part[wid] = acc;
    __syncthreads();
    if (tid == 0) {
        float tot = part[0] + part[1] + part[2] + part[3];
        g_scale[bc] = CONV_SCALE * rsqrtf(CONV_SCALE * CONV_SCALE * tot + EPS_);
    }
}

// ---------------- kernel 3: modulate + transpose + pad x ----------------
// g_xt[b][row*66 + 1 + w][ci] = tf32(x[b][ci][row*64+w] * s[b][ci]); cols 0 and 65 zero.
__global__ void modxt_kernel(const float* __restrict__ x) {
    int row = blockIdx.x, b = blockIdx.y;
    __shared__ float t[64][65];
    float* obase = g_xt + ((size_t)b * MPLANE + (size_t)row * WPAD) * CIN;
    for (int i = threadIdx.x; i < 1024; i += 256) {
        int which = i >> 9, col = i & 511;
        obase[(size_t)which * 65 * CIN + col] = 0.f;   // w'=0 and w'=65 pad rows
    }
    for (int cic = 0; cic < 8; ++cic) {
        __syncthreads();
        for (int i = threadIdx.x; i < 4096; i += 256) {
            int ci = i >> 6, w = i & 63;
            float s = g_s[b * 512 + cic * 64 + ci];
            t[ci][w] = x[((size_t)(b * 512 + cic * 64 + ci)) * HW2 + row * 64 + w] * s;
        }
        __syncthreads();
        for (int i = threadIdx.x; i < 4096; i += 256) {
            int w = i >> 6, ci = i & 63;
            obase[(size_t)(1 + w) * CIN + cic * 64 + ci] = __uint_as_float(tf32r(t[ci][w]));
        }
    }
}

// ---------------- kernel 4: weight transpose [tap][co][ci] ----------------
__global__ void wtrans_kernel(const float* __restrict__ weight) {
    int co = blockIdx.x;
    const float* wrow = weight + (size_t)co * CIN * 9;
    for (int i = threadIdx.x; i < CIN * 9; i += 256) {
        int ci = i / 9, tap = i - ci * 9;
        g_wt[((size_t)tap * COUT + co) * CIN + ci] = __uint_as_float(tf32r(wrow[ci * 9 + tap]));
    }
}

// ---------------- kernel 5: conv as tf32 GEMM ----------------
// CTA: 128 padded-pixels x 128 co, K = 9 taps x 512 ci. 256 threads, 8 warps (2x4),
// warp tile 64m x 32n, mma m16n8k8. Double-buffered cp.async stages of BK=32.
#define BM 128
#define BN 128
#define BK 32
#define PADR 36                    // smem row stride (floats)
#define STAGE_F (128 * PADR)       // floats per stage buffer
#define NSTAGES 144                // 9 taps * 16 k-chunks

__global__ __launch_bounds__(256, 2)
void conv_kernel(float* __restrict__ out) {
    extern __shared__ float sm[];
    float* As = sm;                      // [2][128][PADR]
    float* Bs = sm + 2 * STAGE_F;        // [2][128][PADR]

    const int tid = threadIdx.x;
    const int warp = tid >> 5, lane = tid & 31;
    const int wm = warp & 1;             // 0..1 -> 64-row half
    const int wn = warp >> 1;            // 0..3 -> 32-col slice
    const int lr = lane >> 2;            // 0..7
    const int lc = lane & 3;             // 0..3

    const int co0 = blockIdx.x * BN;
    const int p0 = blockIdx.y * BM;
    const int b = blockIdx.z;

    const float* Abase = g_xt + (size_t)b * MPLANE * CIN;
    const uint32_t as_u = smem_u32(As);
    const uint32_t bs_u = smem_u32(Bs);

    float d[4][4][4];
#pragma unroll
    for (int i = 0; i < 4; ++i)
#pragma unroll
        for (int j = 0; j < 4; ++j)
#pragma unroll
            for (int k = 0; k < 4; ++k) d[i][j][k] = 0.f;

    // ---- stage loader: stage s = tap*16 + kc ----
    auto load_stage = [&](int s, int buf) {
        int tap = s >> 4, kc = s & 15;
        int koff = (tap / 3 - 1) * WPAD + (tap % 3 - 1);
#pragma unroll
        for (int i = 0; i < 4; ++i) {
            int idx = tid + i * 256;
            int row = idx >> 3, q = idx & 7;
            int pr = p0 + row + koff;
            const float* src = Abase + ((size_t)pr * CIN + kc * 32 + q * 4);
            int sz = ((unsigned)pr < (unsigned)MPLANE) ? 16 : 0;
            cp16(as_u + (uint32_t)(buf * STAGE_F + row * PADR + q * 4) * 4u, src, sz);
        }
#pragma unroll
        for (int i = 0; i < 4; ++i) {
            int idx = tid + i * 256;
            int row = idx >> 3, q = idx & 7;
            const float* src = g_wt + (((size_t)tap * COUT + co0 + row) * CIN + kc * 32 + q * 4);
            cp16(bs_u + (uint32_t)(buf * STAGE_F + row * PADR + q * 4) * 4u, src, 16);
        }
        CP_COMMIT();
    };

    load_stage(0, 0);

    for (int s = 0; s < NSTAGES; ++s) {
        int buf = s & 1;
        if (s + 1 < NSTAGES) {
            load_stage(s + 1, buf ^ 1);
            CP_WAIT(1);
        } else {
            CP_WAIT(0);
        }
        __syncthreads();

        const float* A = As + buf * STAGE_F;
        const float* Bm = Bs + buf * STAGE_F;
#pragma unroll
        for (int ks = 0; ks < 4; ++ks) {
            int kb = ks * 8;
            uint32_t a[4][4];
#pragma unroll
            for (int fm = 0; fm < 4; ++fm) {
                int r = wm * 64 + fm * 16 + lr;
                const float* ap = A + r * PADR + kb + lc;
                a[fm][0] = *(const uint32_t*)(ap);
                a[fm][1] = *(const uint32_t*)(ap + 8 * PADR);
                a[fm][2] = *(const uint32_t*)(ap + 4);
                a[fm][3] = *(const uint32_t*)(ap + 8 * PADR + 4);
            }
            uint32_t bf[4][2];
#pragma unroll
            for (int fn = 0; fn < 4; ++fn) {
                int c = wn * 32 + fn * 8 + lr;
                const float* bp = Bm + c * PADR + kb + lc;
                bf[fn][0] = *(const uint32_t*)(bp);
                bf[fn][1] = *(const uint32_t*)(bp + 4);
            }
#pragma unroll
            for (int fm = 0; fm < 4; ++fm)
#pragma unroll
                for (int fn = 0; fn < 4; ++fn)
                    mma_tf32(d[fm][fn], a[fm], bf[fn]);
        }
        __syncthreads();
    }

    // ---- epilogue: transpose through smem, coalesced scaled stores ----
    float* smT = sm;    // [128 co][132 pix]
#pragma unroll
    for (int fm = 0; fm < 4; ++fm) {
#pragma unroll
        for (int fn = 0; fn < 4; ++fn) {
            int m = wm * 64 + fm * 16 + lr;
            int n = wn * 32 + fn * 8 + (lc << 1);
            smT[n * 132 + m]           = d[fm][fn][0];
            smT[(n + 1) * 132 + m]     = d[fm][fn][1];
            smT[n * 132 + m + 8]       = d[fm][fn][2];
            smT[(n + 1) * 132 + m + 8] = d[fm][fn][3];
        }
    }
    __syncthreads();

#pragma unroll 4
    for (int i = 0; i < 64; ++i) {
        int idx = i * 256 + tid;
        int co = idx >> 7, pix = idx & 127;
        int pp = p0 + pix;
        int r = pp / WPAD;
        int w = pp - r * WPAD;
        if (w >= 1 && w <= 64) {
            float sc = g_scale[b * 512 + co0 + co];
            out[((size_t)(b * 512 + co0 + co)) * HW2 + r * 64 + (w - 1)] =
                smT[co * 132 + pix] * sc;
        }
    }
}

// ---------------- launch ----------------
extern "C" void kernel_launch(void* const* d_in, const int* in_sizes, int n_in,
                              void* d_out, int out_size) {
    const float* x      = (const float*)d_in[0];
    const float* style  = (const float*)d_in[1];
    const float* weight = (const float*)d_in[2];
    const float* modw   = (const float*)d_in[3];
    const float* modb   = (const float*)d_in[4];
    float* out = (float*)d_out;
    float* out_s5 = out + (size_t)B_ * COUT * HW2;

    static int smem_set = 0;
    if (!smem_set) {
        cudaFuncSetAttribute(conv_kernel, cudaFuncAttributeMaxDynamicSharedMemorySize,
                             4 * STAGE_F * 4);
        smem_set = 1;
    }

    style_kernel<<<B_, 512>>>(style, modw, modb, out_s5);
    demod_kernel<<<B_ * COUT, 128>>>(weight);
    modxt_kernel<<<dim3(64, B_), 256>>>(x);
    wtrans_kernel<<<COUT, 256>>>(weight);

    dim3 grid(COUT / BN, MPLANE / BM, B_);   // 4 x 33 x 8 = 1056 CTAs
    conv_kernel<<<grid, 256, 4 * STAGE_F * 4>>>(out);
}

// round 4
// speedup vs baseline: 8.3654x; 1.7404x over previous
#include <cuda_runtime.h>
#include <cuda_fp16.h>
#include <cstdint>

// ModulatedConv2d B=8, Cin=Cout=512, K=3, H=W=64
// fp16 mma.sync m16n8k16 implicit GEMM, fp32 accumulate.

#define B_      8
#define CIN     512
#define COUT    512
#define HW2     4096
#define WPAD    66
#define MPLANE  4224        // 64 rows * 66
#define LIN_SCALE   0.044194173824159216f
#define CONV_SCALE  0.014731391274719739f
#define EPS_        1e-8f

// ---------------- device scratch ----------------
__device__ float  g_s[B_ * CIN];
__device__ float  g_scale[B_ * COUT];
__device__ float  g_wsq[COUT * CIN];                       // sum_k w^2 per (co,ci)
__device__ __half g_xt[(size_t)B_ * MPLANE * CIN];         // modulated, transposed, padded
__device__ __half g_wt[9ull * COUT * CIN];                 // [tap][co][ci]

// ---------------- helpers ----------------
__device__ __forceinline__ uint32_t smem_u32(const void* p) {
    uint32_t a;
    asm("{ .reg .u64 t; cvta.to.shared.u64 t, %1; cvt.u32.u64 %0, t; }" : "=r"(a) : "l"(p));
    return a;
}
__device__ __forceinline__ void cp16(uint32_t dst, const void* src, int srcsize) {
    asm volatile("cp.async.ca.shared.global [%0], [%1], 16, %2;"
                 :: "r"(dst), "l"(src), "r"(srcsize) : "memory");
}
#define CP_COMMIT() asm volatile("cp.async.commit_group;" ::: "memory")
#define CP_WAIT(n)  asm volatile("cp.async.wait_group %0;" :: "n"(n) : "memory")

__device__ __forceinline__ void mma_f16(float* d, const uint32_t* a, const uint32_t* b) {
    asm volatile(
        "mma.sync.aligned.m16n8k16.row.col.f32.f16.f16.f32 "
        "{%0,%1,%2,%3}, {%4,%5,%6,%7}, {%8,%9}, {%0,%1,%2,%3};"
        : "+f"(d[0]), "+f"(d[1]), "+f"(d[2]), "+f"(d[3])
        : "r"(a[0]), "r"(a[1]), "r"(a[2]), "r"(a[3]), "r"(b[0]), "r"(b[1]));
}

// ---------------- kernel 1: style modulation ----------------
// grid (B, 8), block 256: 64 ci per block, 4 lanes per ci.
__global__ void style_kernel(const float* __restrict__ style,
                             const float* __restrict__ modw,
                             const float* __restrict__ modb,
                             float* __restrict__ out_s5) {
    __shared__ float st[512];
    int b = blockIdx.x, t = threadIdx.x;
    st[t] = style[b * 512 + t];
    st[t + 256] = style[b * 512 + t + 256];
    __syncthreads();
    int ci = blockIdx.y * 64 + (t >> 2);
    int part = t & 3;
    const float4* mrow = (const float4*)(modw + (size_t)ci * 512) + part * 32;
    const float4* s4 = (const float4*)st + part * 32;
    float a0 = 0.f, a1 = 0.f, a2 = 0.f, a3 = 0.f;
#pragma unroll
    for (int j = 0; j < 32; ++j) {
        float4 m = mrow[j], s = s4[j];
        a0 = fmaf(s.x, m.x, a0);
        a1 = fmaf(s.y, m.y, a1);
        a2 = fmaf(s.z, m.z, a2);
        a3 = fmaf(s.w, m.w, a3);
    }
    float acc = (a0 + a1) + (a2 + a3);
    acc += __shfl_xor_sync(0xffffffffu, acc, 1);
    acc += __shfl_xor_sync(0xffffffffu, acc, 2);
    if (part == 0) {
        float s = acc * LIN_SCALE + modb[ci];
        g_s[b * 512 + ci] = s;
        out_s5[b * 512 + ci] = s;
    }
}

// ---------------- kernel 2: weight transpose + wsq ----------------
__global__ void wtrans_kernel(const float* __restrict__ weight) {
    int co = blockIdx.x, ci = threadIdx.x;
    const float* wp = weight + ((size_t)co * 512 + ci) * 9;
    float w[9], q = 0.f;
#pragma unroll
    for (int k = 0; k < 9; ++k) { w[k] = wp[k]; q = fmaf(w[k], w[k], q); }
    g_wsq[co * 512 + ci] = q;
#pragma unroll
    for (int k = 0; k < 9; ++k)
        g_wt[((size_t)k * COUT + co) * 512 + ci] = __float2half_rn(w[k]);
}

// ---------------- kernel 3: demod scales (reads g_wsq) ----------------
// grid (B, 16), block 256: 32 co per block, 8 lanes per co.
__global__ void demod_kernel() {
    __shared__ float s2[512];
    int b = blockIdx.x, t = threadIdx.x;
    float sv = g_s[b * 512 + t];
    s2[t] = sv * sv;
    sv = g_s[b * 512 + t + 256];
    s2[t + 256] = sv * sv;
    __syncthreads();
    int co = blockIdx.y * 32 + (t >> 3);
    int part = t & 7;
    const float4* wq = (const float4*)(g_wsq + (size_t)co * 512) + part * 16;
    const float4* s4 = (const float4*)s2 + part * 16;
    float a0 = 0.f, a1 = 0.f, a2 = 0.f, a3 = 0.f;
#pragma unroll
    for (int j = 0; j < 16; ++j) {
        float4 m = wq[j], s = s4[j];
        a0 = fmaf(s.x, m.x, a0);
        a1 = fmaf(s.y, m.y, a1);
        a2 = fmaf(s.z, m.z, a2);
        a3 = fmaf(s.w, m.w, a3);
    }
    float acc = (a0 + a1) + (a2 + a3);
    acc += __shfl_xor_sync(0xffffffffu, acc, 1);
    acc += __shfl_xor_sync(0xffffffffu, acc, 2);
    acc += __shfl_xor_sync(0xffffffffu, acc, 4);
    if (part == 0)
        g_scale[b * 512 + co] = CONV_SCALE * rsqrtf(CONV_SCALE * CONV_SCALE * acc + EPS_);
}

// ---------------- kernel 4: modulate + transpose + pad x (fp16) ----------------
__global__ void modxt_kernel(const float* __restrict__ x) {
    int row = blockIdx.x, b = blockIdx.y;
    __shared__ float t[64][65];
    __half* obase = g_xt + ((size_t)b * MPLANE + (size_t)row * WPAD) * CIN;
    for (int i = threadIdx.x; i < 1024; i += 256) {
        int which = i >> 9, col = i & 511;
        obase[(size_t)which * 65 * CIN + col] = __float2half_rn(0.f);
    }
    for (int cic = 0; cic < 8; ++cic) {
        __syncthreads();
        for (int i = threadIdx.x; i < 4096; i += 256) {
            int ci = i >> 6, w = i & 63;
            float s = g_s[b * 512 + cic * 64 + ci];
            t[ci][w] = x[((size_t)(b * 512 + cic * 64 + ci)) * HW2 + row * 64 + w] * s;
        }
        __syncthreads();
        for (int i = threadIdx.x; i < 4096; i += 256) {
            int w = i >> 6, ci = i & 63;
            obase[(size_t)(1 + w) * CIN + cic * 64 + ci] = __float2half_rn(t[ci][w]);
        }
    }
}

// ---------------- kernel 5: conv as fp16 GEMM ----------------
// CTA: 128 padded-pixels x 256 co, K = 9 taps x 512 ci, BK=64 (72 stages).
// 256 threads, 8 warps (2m x 4n), warp tile 64x64, mma m16n8k16.
#define BM 128
#define BN 256
#define KSTR 72                      // smem stride in halves (64 + 8 pad)
#define ASTAGE (BM * KSTR)           // halves
#define BSTAGE (BN * KSTR)
#define NSTAGES 72
#define SMEM_TOTAL 135168            // max(stage bufs 110592, smT 256*132*4)

__global__ __launch_bounds__(256, 1)
void conv_kernel(float* __restrict__ out) {
    extern __shared__ char smch[];
    __half* As = (__half*)smch;                            // [2][ASTAGE]
    __half* Bs = (__half*)(smch + 2 * ASTAGE * 2);         // [2][BSTAGE]

    const int tid = threadIdx.x;
    const int warp = tid >> 5, lane = tid & 31;
    const int wm = warp & 1;
    const int wn = warp >> 1;
    const int gid = lane >> 2;
    const int tig = lane & 3;

    const int co0 = blockIdx.x * BN;
    const int p0 = blockIdx.y * BM;
    const int b = blockIdx.z;

    const __half* Abase = g_xt + (size_t)b * MPLANE * CIN;
    const uint32_t as_u = smem_u32(As);
    const uint32_t bs_u = smem_u32(Bs);

    float d[4][8][4];
#pragma unroll
    for (int i = 0; i < 4; ++i)
#pragma unroll
        for (int j = 0; j < 8; ++j)
#pragma unroll
            for (int k = 0; k < 4; ++k) d[i][j][k] = 0.f;

    auto load_stage = [&](int s, int buf) {
        int tap = s >> 3, kc = s & 7;
        int koff = (tap / 3 - 1) * WPAD + (tap % 3) - 1;
#pragma unroll
        for (int i = 0; i < 4; ++i) {
            int idx = tid + i * 256;             // 0..1023
            int row = idx >> 3, q = idx & 7;
            int pr = p0 + row + koff;
            const __half* src = Abase + (size_t)pr * CIN + kc * 64 + q * 8;
            int sz = ((unsigned)pr < (unsigned)MPLANE) ? 16 : 0;
            cp16(as_u + (uint32_t)(buf * ASTAGE + row * KSTR + q * 8) * 2u, src, sz);
        }
#pragma unroll
        for (int i = 0; i < 8; ++i) {
            int idx = tid + i * 256;             // 0..2047
            int row = idx >> 3, q = idx & 7;
            const __half* src = g_wt + ((size_t)tap * COUT + co0 + row) * CIN + kc * 64 + q * 8;
            cp16(bs_u + (uint32_t)(buf * BSTAGE + row * KSTR + q * 8) * 2u, src, 16);
        }
        CP_COMMIT();
    };

    load_stage(0, 0);

    for (int s = 0; s < NSTAGES; ++s) {
        int buf = s & 1;
        if (s + 1 < NSTAGES) {
            load_stage(s + 1, buf ^ 1);
            CP_WAIT(1);
        } else {
            CP_WAIT(0);
        }
        __syncthreads();

        const __half* A = As + buf * ASTAGE;
        const __half* Bm = Bs + buf * BSTAGE;
#pragma unroll
        for (int ks = 0; ks < 4; ++ks) {
            int kb = ks * 16;
            uint32_t a[4][4];
#pragma unroll
            for (int fm = 0; fm < 4; ++fm) {
                int r = wm * 64 + fm * 16 + gid;
                const __half* ap = A + r * KSTR + kb + tig * 2;
                a[fm][0] = *(const uint32_t*)(ap);
                a[fm][1] = *(const uint32_t*)(ap + 8 * KSTR);
                a[fm][2] = *(const uint32_t*)(ap + 8);
                a[fm][3] = *(const uint32_t*)(ap + 8 * KSTR + 8);
            }
            uint32_t bf[8][2];
#pragma unroll
            for (int fn = 0; fn < 8; ++fn) {
                int c = wn * 64 + fn * 8 + gid;
                const __half* bp = Bm + c * KSTR + kb + tig * 2;
                bf[fn][0] = *(const uint32_t*)(bp);
                bf[fn][1] = *(const uint32_t*)(bp + 8);
            }
#pragma unroll
            for (int fm = 0; fm < 4; ++fm)
#pragma unroll
                for (int fn = 0; fn < 8; ++fn)
                    mma_f16(d[fm][fn], a[fm], bf[fn]);
        }
        __syncthreads();
    }

    // ---- epilogue: transpose through smem, coalesced scaled stores ----
    float* smT = (float*)smch;    // [256 co][132 pix]
#pragma unroll
    for (int fm = 0; fm < 4; ++fm) {
#pragma unroll
        for (int fn = 0; fn < 8; ++fn) {
            int m = wm * 64 + fm * 16 + gid;
            int n = wn * 64 + fn * 8 + tig * 2;
            smT[n * 132 + m]           = d[fm][fn][0];
            smT[(n + 1) * 132 + m]     = d[fm][fn][1];
            smT[n * 132 + m + 8]       = d[fm][fn][2];
            smT[(n + 1) * 132 + m + 8] = d[fm][fn][3];
        }
    }
    __syncthreads();

#pragma unroll 4
    for (int i = 0; i < 128; ++i) {
        int idx = i * 256 + tid;
        int co = idx >> 7, pix = idx & 127;
        int pp = p0 + pix;
        int r = pp / WPAD;
        int w = pp - r * WPAD;
        if (w >= 1 && w <= 64) {
            float sc = g_scale[b * 512 + co0 + co];
            out[((size_t)(b * 512 + co0 + co)) * HW2 + r * 64 + (w - 1)] =
                smT[co * 132 + pix] * sc;
        }
    }
}

// ---------------- launch ----------------
extern "C" void kernel_launch(void* const* d_in, const int* in_sizes, int n_in,
                              void* d_out, int out_size) {
    const float* x      = (const float*)d_in[0];
    const float* style  = (const float*)d_in[1];
    const float* weight = (const float*)d_in[2];
    const float* modw   = (const float*)d_in[3];
    const float* modb   = (const float*)d_in[4];
    float* out = (float*)d_out;
    float* out_s5 = out + (size_t)B_ * COUT * HW2;

    static int smem_set = 0;
    if (!smem_set) {
        cudaFuncSetAttribute(conv_kernel, cudaFuncAttributeMaxDynamicSharedMemorySize,
                             SMEM_TOTAL);
        smem_set = 1;
    }

    style_kernel<<<dim3(B_, 8), 256>>>(style, modw, modb, out_s5);
    wtrans_kernel<<<COUT, 512>>>(weight);
    demod_kernel<<<dim3(B_, 16), 256>>>();
    modxt_kernel<<<dim3(64, B_), 256>>>(x);

    dim3 grid(COUT / BN, MPLANE / BM, B_);   // 2 x 33 x 8 = 528 CTAs
    conv_kernel<<<grid, 256, SMEM_TOTAL>>>(out);
}

// round 5
// speedup vs baseline: 8.9378x; 1.0684x over previous
#include <cuda_runtime.h>
#include <cuda_fp16.h>
#include <cstdint>

// ModulatedConv2d B=8, Cin=Cout=512, K=3, H=W=64
// fp16 mma.sync m16n8k16 implicit GEMM, fp32 accumulate, ldmatrix + 3-stage cp.async ring.

#define B_      8
#define CIN     512
#define COUT    512
#define HW2     4096
#define WPAD    66
#define MPLANE  4224        // 64 rows * 66
#define LIN_SCALE   0.044194173824159216f
#define CONV_SCALE  0.014731391274719739f
#define EPS_        1e-8f

// ---------------- device scratch ----------------
__device__ float  g_s[B_ * CIN];
__device__ float  g_scale[B_ * COUT];
__device__ float  g_wsq[COUT * CIN];
__device__ __half g_xt[(size_t)B_ * MPLANE * CIN];
__device__ __half g_wt[9ull * COUT * CIN];

// ---------------- helpers ----------------
__device__ __forceinline__ uint32_t smem_u32(const void* p) {
    uint32_t a;
    asm("{ .reg .u64 t; cvta.to.shared.u64 t, %1; cvt.u32.u64 %0, t; }" : "=r"(a) : "l"(p));
    return a;
}
__device__ __forceinline__ void cp16(uint32_t dst, const void* src, int srcsize) {
    asm volatile("cp.async.ca.shared.global [%0], [%1], 16, %2;"
                 :: "r"(dst), "l"(src), "r"(srcsize) : "memory");
}
#define CP_COMMIT() asm volatile("cp.async.commit_group;" ::: "memory")
#define CP_WAIT(n)  asm volatile("cp.async.wait_group %0;" :: "n"(n) : "memory")

__device__ __forceinline__ void ldsm4(uint32_t* r, uint32_t addr) {
    asm volatile("ldmatrix.sync.aligned.m8n8.x4.shared.b16 {%0,%1,%2,%3}, [%4];"
        : "=r"(r[0]), "=r"(r[1]), "=r"(r[2]), "=r"(r[3]) : "r"(addr));
}
__device__ __forceinline__ void mma_f16(float* d, const uint32_t* a, const uint32_t* b) {
    asm volatile(
        "mma.sync.aligned.m16n8k16.row.col.f32.f16.f16.f32 "
        "{%0,%1,%2,%3}, {%4,%5,%6,%7}, {%8,%9}, {%0,%1,%2,%3};"
        : "+f"(d[0]), "+f"(d[1]), "+f"(d[2]), "+f"(d[3])
        : "r"(a[0]), "r"(a[1]), "r"(a[2]), "r"(a[3]), "r"(b[0]), "r"(b[1]));
}

// ---------------- prep1: style (blocks 0..31) + wtrans (blocks 32..543), 512 thr ----
__global__ void prep1_kernel(const float* __restrict__ style,
                             const float* __restrict__ modw,
                             const float* __restrict__ modb,
                             const float* __restrict__ weight,
                             float* __restrict__ out_s5) {
    int blk = blockIdx.x, t = threadIdx.x;
    if (blk < 32) {
        __shared__ float st[512];
        int b = blk >> 2;
        st[t] = style[b * 512 + t];
        __syncthreads();
        int ci = (blk & 3) * 128 + (t >> 2);
        int part = t & 3;
        const float4* mrow = (const float4*)(modw + (size_t)ci * 512) + part * 32;
        const float4* s4 = (const float4*)st + part * 32;
        float a0 = 0.f, a1 = 0.f, a2 = 0.f, a3 = 0.f;
#pragma unroll
        for (int j = 0; j < 32; ++j) {
            float4 m = mrow[j], s = s4[j];
            a0 = fmaf(s.x, m.x, a0);
            a1 = fmaf(s.y, m.y, a1);
            a2 = fmaf(s.z, m.z, a2);
            a3 = fmaf(s.w, m.w, a3);
        }
        float acc = (a0 + a1) + (a2 + a3);
        acc += __shfl_xor_sync(0xffffffffu, acc, 1);
        acc += __shfl_xor_sync(0xffffffffu, acc, 2);
        if (part == 0) {
            float s = acc * LIN_SCALE + modb[ci];
            g_s[b * 512 + ci] = s;
            out_s5[b * 512 + ci] = s;
        }
    } else {
        int co = blk - 32, ci = t;
        const float* wp = weight + ((size_t)co * 512 + ci) * 9;
        float w[9], q = 0.f;
#pragma unroll
        for (int k = 0; k < 9; ++k) { w[k] = wp[k]; q = fmaf(w[k], w[k], q); }
        g_wsq[co * 512 + ci] = q;
#pragma unroll
        for (int k = 0; k < 9; ++k)
            g_wt[((size_t)k * COUT + co) * 512 + ci] = __float2half_rn(w[k]);
    }
}

// ---------------- prep2: demod (blocks 0..127) + modxt (blocks 128..639), 256 thr ----
__global__ void prep2_kernel(const float* __restrict__ x) {
    int blk = blockIdx.x, t = threadIdx.x;
    if (blk < 128) {
        __shared__ float s2[512];
        int b = blk >> 4;
        float sv = g_s[b * 512 + t];
        s2[t] = sv * sv;
        sv = g_s[b * 512 + t + 256];
        s2[t + 256] = sv * sv;
        __syncthreads();
        int co = (blk & 15) * 32 + (t >> 3);
        int part = t & 7;
        const float4* wq = (const float4*)(g_wsq + (size_t)co * 512) + part * 16;
        const float4* s4 = (const float4*)s2 + part * 16;
        float a0 = 0.f, a1 = 0.f, a2 = 0.f, a3 = 0.f;
#pragma unroll
        for (int j = 0; j < 16; ++j) {
            float4 m = wq[j], s = s4[j];
            a0 = fmaf(s.x, m.x, a0);
            a1 = fmaf(s.y, m.y, a1);
            a2 = fmaf(s.z, m.z, a2);
            a3 = fmaf(s.w, m.w, a3);
        }
        float acc = (a0 + a1) + (a2 + a3);
        acc += __shfl_xor_sync(0xffffffffu, acc, 1);
        acc += __shfl_xor_sync(0xffffffffu, acc, 2);
        acc += __shfl_xor_sync(0xffffffffu, acc, 4);
        if (part == 0)
            g_scale[b * 512 + co] = CONV_SCALE * rsqrtf(CONV_SCALE * CONV_SCALE * acc + EPS_);
    } else {
        __shared__ float tt[64][65];
        int idx = blk - 128;
        int row = idx & 63, b = idx >> 6;
        __half* obase = g_xt + ((size_t)b * MPLANE + (size_t)row * WPAD) * CIN;
        for (int i = t; i < 1024; i += 256) {
            int which = i >> 9, col = i & 511;
            obase[(size_t)which * 65 * CIN + col] = __float2half_rn(0.f);
        }
        for (int cic = 0; cic < 8; ++cic) {
            __syncthreads();
            for (int i = t; i < 4096; i += 256) {
                int ci = i >> 6, w = i & 63;
                float s = g_s[b * 512 + cic * 64 + ci];
                tt[ci][w] = x[((size_t)(b * 512 + cic * 64 + ci)) * HW2 + row * 64 + w] * s;
            }
            __syncthreads();
            for (int i = t; i < 4096; i += 256) {
                int w = i >> 6, ci = i & 63;
                obase[(size_t)(1 + w) * CIN + cic * 64 + ci] = __float2half_rn(tt[ci][w]);
            }
        }
    }
}

// ---------------- conv: fp16 GEMM, 3-stage ring, ldmatrix ----------------
#define BM 128
#define BN 256
#define KSTR 72                      // smem stride in halves
#define ASTAGE (BM * KSTR)
#define BSTAGE (BN * KSTR)
#define NSTAGES 72
#define SMEM_TOTAL 165888            // 3*(ASTAGE+BSTAGE)*2

__global__ __launch_bounds__(256, 1)
void conv_kernel(float* __restrict__ out) {
    extern __shared__ char smch[];
    __half* As = (__half*)smch;                            // [3][ASTAGE]
    __half* Bs = (__half*)(smch + 3 * ASTAGE * 2);         // [3][BSTAGE]

    const int tid = threadIdx.x;
    const int warp = tid >> 5, lane = tid & 31;
    const int wm = warp & 1;
    const int wn = warp >> 1;
    const int gid = lane >> 2;
    const int tig = lane & 3;

    const int co0 = blockIdx.x * BN;
    const int p0 = blockIdx.y * BM;
    const int b = blockIdx.z;

    const __half* Abase = g_xt + (size_t)b * MPLANE * CIN;
    const uint32_t as_u = smem_u32(As);
    const uint32_t bs_u = smem_u32(Bs);

    // ldmatrix lane offsets (in halves)
    const uint32_t a_loff = ((lane & 7) + ((lane >> 3) & 1) * 8) * KSTR + (lane >> 4) * 8;
    const uint32_t b_loff = ((lane & 7) + ((lane >> 4) & 1) * 8) * KSTR + ((lane >> 3) & 1) * 8;

    float d[4][8][4];
#pragma unroll
    for (int i = 0; i < 4; ++i)
#pragma unroll
        for (int j = 0; j < 8; ++j)
#pragma unroll
            for (int k = 0; k < 4; ++k) d[i][j][k] = 0.f;

    auto load_stage = [&](int s, int buf) {
        int tap = s >> 3, kc = s & 7;
        int koff = (tap / 3 - 1) * WPAD + (tap % 3) - 1;
#pragma unroll
        for (int i = 0; i < 4; ++i) {
            int idx = tid + i * 256;
            int row = idx >> 3, q = idx & 7;
            int pr = p0 + row + koff;
            const __half* src = Abase + (size_t)pr * CIN + kc * 64 + q * 8;
            int sz = ((unsigned)pr < (unsigned)MPLANE) ? 16 : 0;
            cp16(as_u + (uint32_t)(buf * ASTAGE + row * KSTR + q * 8) * 2u, src, sz);
        }
#pragma unroll
        for (int i = 0; i < 8; ++i) {
            int idx = tid + i * 256;
            int row = idx >> 3, q = idx & 7;
            const __half* src = g_wt + ((size_t)tap * COUT + co0 + row) * CIN + kc * 64 + q * 8;
            cp16(bs_u + (uint32_t)(buf * BSTAGE + row * KSTR + q * 8) * 2u, src, 16);
        }
        CP_COMMIT();
    };

    load_stage(0, 0);
    load_stage(1, 1);

    for (int s = 0; s < NSTAGES; ++s) {
        CP_WAIT(1);
        __syncthreads();
        if (s + 2 < NSTAGES) load_stage(s + 2, (s + 2) % 3);

        const int buf = s % 3;
        const uint32_t abase = as_u + (uint32_t)(buf * ASTAGE) * 2u;
        const uint32_t bbase = bs_u + (uint32_t)(buf * BSTAGE) * 2u;
#pragma unroll
        for (int ks = 0; ks < 4; ++ks) {
            const int kb = ks * 16;
            uint32_t a[4][4];
#pragma unroll
            for (int fm = 0; fm < 4; ++fm)
                ldsm4(a[fm], abase + ((uint32_t)((wm * 64 + fm * 16) * KSTR + kb) + a_loff) * 2u);
            uint32_t bf[8][2];
#pragma unroll
            for (int j = 0; j < 4; ++j) {
                uint32_t r[4];
                ldsm4(r, bbase + ((uint32_t)((wn * 64 + j * 16) * KSTR + kb) + b_loff) * 2u);
                bf[2 * j][0] = r[0]; bf[2 * j][1] = r[1];
                bf[2 * j + 1][0] = r[2]; bf[2 * j + 1][1] = r[3];
            }
#pragma unroll
            for (int fm = 0; fm < 4; ++fm)
#pragma unroll
                for (int fn = 0; fn < 8; ++fn)
                    mma_f16(d[fm][fn], a[fm], bf[fn]);
        }
    }

    // ---- epilogue: transpose through smem, coalesced scaled stores ----
    __syncthreads();
    float* smT = (float*)smch;    // [256 co][132 pix]
#pragma unroll
    for (int fm = 0; fm < 4; ++fm) {
#pragma unroll
        for (int fn = 0; fn < 8; ++fn) {
            int m = wm * 64 + fm * 16 + gid;
            int n = wn * 64 + fn * 8 + tig * 2;
            smT[n * 132 + m]           = d[fm][fn][0];
            smT[(n + 1) * 132 + m]     = d[fm][fn][1];
            smT[n * 132 + m + 8]       = d[fm][fn][2];
            smT[(n + 1) * 132 + m + 8] = d[fm][fn][3];
        }
    }
    __syncthreads();

#pragma unroll 4
    for (int i = 0; i < 128; ++i) {
        int idx = i * 256 + tid;
        int co = idx >> 7, pix = idx & 127;
        int pp = p0 + pix;
        int r = pp / WPAD;
        int w = pp - r * WPAD;
        if (w >= 1 && w <= 64) {
            float sc = g_scale[b * 512 + co0 + co];
            out[((size_t)(b * 512 + co0 + co)) * HW2 + r * 64 + (w - 1)] =
                smT[co * 132 + pix] * sc;
        }
    }
}

// ---------------- launch ----------------
extern "C" void kernel_launch(void* const* d_in, const int* in_sizes, int n_in,
                              void* d_out, int out_size) {
    const float* x      = (const float*)d_in[0];
    const float* style  = (const float*)d_in[1];
    const float* weight = (const float*)d_in[2];
    const float* modw   = (const float*)d_in[3];
    const float* modb   = (const float*)d_in[4];
    float* out = (float*)d_out;
    float* out_s5 = out + (size_t)B_ * COUT * HW2;

    static int smem_set = 0;
    if (!smem_set) {
        cudaFuncSetAttribute(conv_kernel, cudaFuncAttributeMaxDynamicSharedMemorySize,
                             SMEM_TOTAL);
        smem_set = 1;
    }

    prep1_kernel<<<544, 512>>>(style, modw, modb, weight, out_s5);
    prep2_kernel<<<640, 256>>>(x);

    dim3 grid(COUT / BN, MPLANE / BM, B_);   // 2 x 33 x 8 = 528 CTAs
    conv_kernel<<<grid, 256, SMEM_TOTAL>>>(out);
}

// round 6
// speedup vs baseline: 9.4515x; 1.0575x over previous
#include <cuda_runtime.h>
#include <cuda_fp16.h>
#include <cstdint>

// ModulatedConv2d B=8, Cin=Cout=512, K=3, H=W=64
// fp16 mma.sync m16n8k16 implicit GEMM, 3-stage cp.async ring, 2 CTAs/SM.

#define B_      8
#define CIN     512
#define COUT    512
#define HW2     4096
#define WPAD    66
#define MPLANE  4224        // 64 rows * 66
#define LIN_SCALE   0.044194173824159216f
#define CONV_SCALE  0.014731391274719739f
#define EPS_        1e-8f

// ---------------- device scratch ----------------
__device__ float  g_s[B_ * CIN];
__device__ float  g_scale[B_ * COUT];
__device__ float  g_wsq[COUT * CIN];
__device__ __half g_xt[(size_t)B_ * MPLANE * CIN];
__device__ __half g_wt[9ull * COUT * CIN];

// ---------------- helpers ----------------
__device__ __forceinline__ uint32_t smem_u32(const void* p) {
    uint32_t a;
    asm("{ .reg .u64 t; cvta.to.shared.u64 t, %1; cvt.u32.u64 %0, t; }" : "=r"(a) : "l"(p));
    return a;
}
__device__ __forceinline__ void cp16(uint32_t dst, const void* src, int srcsize) {
    asm volatile("cp.async.ca.shared.global [%0], [%1], 16, %2;"
                 :: "r"(dst), "l"(src), "r"(srcsize) : "memory");
}
#define CP_COMMIT() asm volatile("cp.async.commit_group;" ::: "memory")
#define CP_WAIT(n)  asm volatile("cp.async.wait_group %0;" :: "n"(n) : "memory")

__device__ __forceinline__ void ldsm4(uint32_t* r, uint32_t addr) {
    asm volatile("ldmatrix.sync.aligned.m8n8.x4.shared.b16 {%0,%1,%2,%3}, [%4];"
        : "=r"(r[0]), "=r"(r[1]), "=r"(r[2]), "=r"(r[3]) : "r"(addr));
}
__device__ __forceinline__ void mma_f16(float* d, const uint32_t* a, const uint32_t* b) {
    asm volatile(
        "mma.sync.aligned.m16n8k16.row.col.f32.f16.f16.f32 "
        "{%0,%1,%2,%3}, {%4,%5,%6,%7}, {%8,%9}, {%0,%1,%2,%3};"
        : "+f"(d[0]), "+f"(d[1]), "+f"(d[2]), "+f"(d[3])
        : "r"(a[0]), "r"(a[1]), "r"(a[2]), "r"(a[3]), "r"(b[0]), "r"(b[1]));
}

// ---------------- prep1: style (blocks 0..31) + wtrans (blocks 32..543), 512 thr ----
__global__ void prep1_kernel(const float* __restrict__ style,
                             const float* __restrict__ modw,
                             const float* __restrict__ modb,
                             const float* __restrict__ weight,
                             float* __restrict__ out_s5) {
    int blk = blockIdx.x, t = threadIdx.x;
    if (blk < 32) {
        __shared__ float st[512];
        int b = blk >> 2;
        st[t] = style[b * 512 + t];
        __syncthreads();
        int ci = (blk & 3) * 128 + (t >> 2);
        int part = t & 3;
        const float4* mrow = (const float4*)(modw + (size_t)ci * 512) + part * 32;
        const float4* s4 = (const float4*)st + part * 32;
        float a0 = 0.f, a1 = 0.f, a2 = 0.f, a3 = 0.f;
#pragma unroll
        for (int j = 0; j < 32; ++j) {
            float4 m = mrow[j], s = s4[j];
            a0 = fmaf(s.x, m.x, a0);
            a1 = fmaf(s.y, m.y, a1);
            a2 = fmaf(s.z, m.z, a2);
            a3 = fmaf(s.w, m.w, a3);
        }
        float acc = (a0 + a1) + (a2 + a3);
        acc += __shfl_xor_sync(0xffffffffu, acc, 1);
        acc += __shfl_xor_sync(0xffffffffu, acc, 2);
        if (part == 0) {
            float s = acc * LIN_SCALE + modb[ci];
            g_s[b * 512 + ci] = s;
            out_s5[b * 512 + ci] = s;
        }
    } else {
        int co = blk - 32, ci = t;
        const float* wp = weight + ((size_t)co * 512 + ci) * 9;
        float w[9], q = 0.f;
#pragma unroll
        for (int k = 0; k < 9; ++k) { w[k] = wp[k]; q = fmaf(w[k], w[k], q); }
        g_wsq[co * 512 + ci] = q;
#pragma unroll
        for (int k = 0; k < 9; ++k)
            g_wt[((size_t)k * COUT + co) * 512 + ci] = __float2half_rn(w[k]);
    }
}

// ---------------- prep2: demod (blocks 0..127) + modxt (blocks 128..2175), 256 thr ----
__global__ void prep2_kernel(const float* __restrict__ x) {
    int blk = blockIdx.x, t = threadIdx.x;
    if (blk < 128) {
        __shared__ float s2[512];
        int b = blk >> 4;
        float sv = g_s[b * 512 + t];
        s2[t] = sv * sv;
        sv = g_s[b * 512 + t + 256];
        s2[t + 256] = sv * sv;
        __syncthreads();
        int co = (blk & 15) * 32 + (t >> 3);
        int part = t & 7;
        const float4* wq = (const float4*)(g_wsq + (size_t)co * 512) + part * 16;
        const float4* s4 = (const float4*)s2 + part * 16;
        float a0 = 0.f, a1 = 0.f, a2 = 0.f, a3 = 0.f;
#pragma unroll
        for (int j = 0; j < 16; ++j) {
            float4 m = wq[j], s = s4[j];
            a0 = fmaf(s.x, m.x, a0);
            a1 = fmaf(s.y, m.y, a1);
            a2 = fmaf(s.z, m.z, a2);
            a3 = fmaf(s.w, m.w, a3);
        }
        float acc = (a0 + a1) + (a2 + a3);
        acc += __shfl_xor_sync(0xffffffffu, acc, 1);
        acc += __shfl_xor_sync(0xffffffffu, acc, 2);
        acc += __shfl_xor_sync(0xffffffffu, acc, 4);
        if (part == 0)
            g_scale[b * 512 + co] = CONV_SCALE * rsqrtf(CONV_SCALE * CONV_SCALE * acc + EPS_);
    } else {
        // modxt: one block per (b, row, 128-ci group)
        __shared__ float tt[64][65];
        int idx = blk - 128;               // 0..2047
        int cg  = idx & 3;                 // 128-ci group
        int row = (idx >> 2) & 63;
        int b   = idx >> 8;
        __half* obase = g_xt + ((size_t)b * MPLANE + (size_t)row * WPAD) * CIN;
        if (t < 256) {                     // zero this slice of the two pad rows
            int which = t >> 7, col = (t & 127) + cg * 128;
            obase[(size_t)which * 65 * CIN + col] = __float2half_rn(0.f);
        }
        for (int cc = 0; cc < 2; ++cc) {
            int cic = cg * 2 + cc;         // 64-ci chunk
            __syncthreads();
            for (int i = t; i < 4096; i += 256) {
                int ci = i >> 6, w = i & 63;
                float s = g_s[b * 512 + cic * 64 + ci];
                tt[ci][w] = x[((size_t)(b * 512 + cic * 64 + ci)) * HW2 + row * 64 + w] * s;
            }
            __syncthreads();
            for (int i = t; i < 4096; i += 256) {
                int w = i >> 6, ci = i & 63;
                obase[(size_t)(1 + w) * CIN + cic * 64 + ci] = __float2half_rn(tt[ci][w]);
            }
        }
    }
}

// ---------------- conv: fp16 GEMM, 3-stage ring, 2 CTAs/SM ----------------
#define BM 128
#define BN 128
#define KSTR 72                      // smem stride in halves
#define ASTAGE (BM * KSTR)
#define BSTAGE (BN * KSTR)
#define NSTAGES 72
#define SMEM_TOTAL 110592            // 3*(ASTAGE+BSTAGE)*2

__global__ __launch_bounds__(256, 2)
void conv_kernel(float* __restrict__ out) {
    extern __shared__ char smch[];
    __half* As = (__half*)smch;                            // [3][ASTAGE]
    __half* Bs = (__half*)(smch + 3 * ASTAGE * 2);         // [3][BSTAGE]

    const int tid = threadIdx.x;
    const int warp = tid >> 5, lane = tid & 31;
    const int wm = warp & 1;
    const int wn = warp >> 1;
    const int gid = lane >> 2;
    const int tig = lane & 3;

    const int co0 = blockIdx.x * BN;
    const int p0 = blockIdx.y * BM;
    const int b = blockIdx.z;

    const __half* Abase = g_xt + (size_t)b * MPLANE * CIN;
    const uint32_t as_u = smem_u32(As);
    const uint32_t bs_u = smem_u32(Bs);

    const uint32_t a_loff = ((lane & 7) + ((lane >> 3) & 1) * 8) * KSTR + (lane >> 4) * 8;
    const uint32_t b_loff = ((lane & 7) + ((lane >> 4) & 1) * 8) * KSTR + ((lane >> 3) & 1) * 8;

    float d[4][4][4];
#pragma unroll
    for (int i = 0; i < 4; ++i)
#pragma unroll
        for (int j = 0; j < 4; ++j)
#pragma unroll
            for (int k = 0; k < 4; ++k) d[i][j][k] = 0.f;

    auto load_stage = [&](int s, int buf) {
        int tap = s >> 3, kc = s & 7;
        int koff = (tap / 3 - 1) * WPAD + (tap % 3) - 1;
#pragma unroll
        for (int i = 0; i < 4; ++i) {
            int idx = tid + i * 256;             // 0..1023: 128 rows x 8 q
            int row = idx >> 3, q = idx & 7;
            int pr = p0 + row + koff;
            const __half* src = Abase + (size_t)pr * CIN + kc * 64 + q * 8;
            int sz = ((unsigned)pr < (unsigned)MPLANE) ? 16 : 0;
            cp16(as_u + (uint32_t)(buf * ASTAGE + row * KSTR + q * 8) * 2u, src, sz);
        }
#pragma unroll
        for (int i = 0; i < 4; ++i) {
            int idx = tid + i * 256;             // 0..1023: 128 rows x 8 q
            int row = idx >> 3, q = idx & 7;
            const __half* src = g_wt + ((size_t)tap * COUT + co0 + row) * CIN + kc * 64 + q * 8;
            cp16(bs_u + (uint32_t)(buf * BSTAGE + row * KSTR + q * 8) * 2u, src, 16);
        }
        CP_COMMIT();
    };

    load_stage(0, 0);
    load_stage(1, 1);

    for (int s = 0; s < NSTAGES; ++s) {
        CP_WAIT(1);
        __syncthreads();
        if (s + 2 < NSTAGES) load_stage(s + 2, (s + 2) % 3);

        const int buf = s % 3;
        const uint32_t abase = as_u + (uint32_t)(buf * ASTAGE) * 2u;
        const uint32_t bbase = bs_u + (uint32_t)(buf * BSTAGE) * 2u;
#pragma unroll
        for (int ks = 0; ks < 4; ++ks) {
            const int kb = ks * 16;
            uint32_t a[4][4];
#pragma unroll
            for (int fm = 0; fm < 4; ++fm)
                ldsm4(a[fm], abase + ((uint32_t)((wm * 64 + fm * 16) * KSTR + kb) + a_loff) * 2u);
            uint32_t bf[4][2];
#pragma unroll
            for (int j = 0; j < 2; ++j) {
                uint32_t r[4];
                ldsm4(r, bbase + ((uint32_t)((wn * 32 + j * 16) * KSTR + kb) + b_loff) * 2u);
                bf[2 * j][0] = r[0]; bf[2 * j][1] = r[1];
                bf[2 * j + 1][0] = r[2]; bf[2 * j + 1][1] = r[3];
            }
#pragma unroll
            for (int fm = 0; fm < 4; ++fm)
#pragma unroll
                for (int fn = 0; fn < 4; ++fn)
                    mma_f16(d[fm][fn], a[fm], bf[fn]);
        }
    }

    // ---- epilogue: transpose through smem, coalesced scaled stores ----
    __syncthreads();
    float* smT = (float*)smch;    // [128 co][132 pix]
#pragma unroll
    for (int fm = 0; fm < 4; ++fm) {
#pragma unroll
        for (int fn = 0; fn < 4; ++fn) {
            int m = wm * 64 + fm * 16 + gid;
            int n = wn * 32 + fn * 8 + tig * 2;
            smT[n * 132 + m]           = d[fm][fn][0];
            smT[(n + 1) * 132 + m]     = d[fm][fn][1];
            smT[n * 132 + m + 8]       = d[fm][fn][2];
            smT[(n + 1) * 132 + m + 8] = d[fm][fn][3];
        }
    }
    __syncthreads();

#pragma unroll 4
    for (int i = 0; i < 64; ++i) {
        int idx = i * 256 + tid;
        int co = idx >> 7, pix = idx & 127;
        int pp = p0 + pix;
        int r = pp / WPAD;
        int w = pp - r * WPAD;
        if (w >= 1 && w <= 64) {
            float sc = g_scale[b * 512 + co0 + co];
            out[((size_t)(b * 512 + co0 + co)) * HW2 + r * 64 + (w - 1)] =
                smT[co * 132 + pix] * sc;
        }
    }
}

// ---------------- launch ----------------
extern "C" void kernel_launch(void* const* d_in, const int* in_sizes, int n_in,
                              void* d_out, int out_size) {
    const float* x      = (const float*)d_in[0];
    const float* style  = (const float*)d_in[1];
    const float* weight = (const float*)d_in[2];
    const float* modw   = (const float*)d_in[3];
    const float* modb   = (const float*)d_in[4];
    float* out = (float*)d_out;
    float* out_s5 = out + (size_t)B_ * COUT * HW2;

    static int smem_set = 0;
    if (!smem_set) {
        cudaFuncSetAttribute(conv_kernel, cudaFuncAttributeMaxDynamicSharedMemorySize,
                             SMEM_TOTAL);
        smem_set = 1;
    }

    prep1_kernel<<<544, 512>>>(style, modw, modb, weight, out_s5);
    prep2_kernel<<<2176, 256>>>(x);

    dim3 grid(COUT / BN, MPLANE / BM, B_);   // 4 x 33 x 8 = 1056 CTAs
    conv_kernel<<<grid, 256, SMEM_TOTAL>>>(out);
}

// round 7
// speedup vs baseline: 10.3822x; 1.0985x over previous
#include <cuda_runtime.h>
#include <cuda_fp16.h>
#include <cstdint>

// ModulatedConv2d B=8, Cin=Cout=512, K=3, H=W=64
// fp16 mma.sync m16n8k16 implicit GEMM; kw-tap-resident stages, 2 CTAs/SM.

#define B_      8
#define CIN     512
#define COUT    512
#define HW2     4096
#define WPAD    66
#define MPLANE  4224        // 64 rows * 66
#define LIN_SCALE   0.044194173824159216f
#define CONV_SCALE  0.014731391274719739f
#define EPS_        1e-8f

// ---------------- device scratch ----------------
__device__ float  g_s[B_ * CIN];
__device__ float  g_scale[B_ * COUT];
__device__ float  g_wsq[COUT * CIN];
__device__ __half g_xt[(size_t)B_ * MPLANE * CIN];
__device__ __half g_wt[9ull * COUT * CIN];

// ---------------- helpers ----------------
__device__ __forceinline__ uint32_t smem_u32(const void* p) {
    uint32_t a;
    asm("{ .reg .u64 t; cvta.to.shared.u64 t, %1; cvt.u32.u64 %0, t; }" : "=r"(a) : "l"(p));
    return a;
}
__device__ __forceinline__ void cp16(uint32_t dst, const void* src, int srcsize) {
    asm volatile("cp.async.ca.shared.global [%0], [%1], 16, %2;"
                 :: "r"(dst), "l"(src), "r"(srcsize) : "memory");
}
#define CP_COMMIT() asm volatile("cp.async.commit_group;" ::: "memory")
#define CP_WAIT(n)  asm volatile("cp.async.wait_group %0;" :: "n"(n) : "memory")

__device__ __forceinline__ void ldsm4(uint32_t* r, uint32_t addr) {
    asm volatile("ldmatrix.sync.aligned.m8n8.x4.shared.b16 {%0,%1,%2,%3}, [%4];"
        : "=r"(r[0]), "=r"(r[1]), "=r"(r[2]), "=r"(r[3]) : "r"(addr));
}
__device__ __forceinline__ void mma_f16(float* d, const uint32_t* a, const uint32_t* b) {
    asm volatile(
        "mma.sync.aligned.m16n8k16.row.col.f32.f16.f16.f32 "
        "{%0,%1,%2,%3}, {%4,%5,%6,%7}, {%8,%9}, {%0,%1,%2,%3};"
        : "+f"(d[0]), "+f"(d[1]), "+f"(d[2]), "+f"(d[3])
        : "r"(a[0]), "r"(a[1]), "r"(a[2]), "r"(a[3]), "r"(b[0]), "r"(b[1]));
}

// ---------------- prep1: style (blocks 0..31) + wtrans (blocks 32..543), 512 thr ----
__global__ void prep1_kernel(const float* __restrict__ style,
                             const float* __restrict__ modw,
                             const float* __restrict__ modb,
                             const float* __restrict__ weight,
                             float* __restrict__ out_s5) {
    int blk = blockIdx.x, t = threadIdx.x;
    if (blk < 32) {
        __shared__ float st[512];
        int b = blk >> 2;
        st[t] = style[b * 512 + t];
        __syncthreads();
        int ci = (blk & 3) * 128 + (t >> 2);
        int part = t & 3;
        const float4* mrow = (const float4*)(modw + (size_t)ci * 512) + part * 32;
        const float4* s4 = (const float4*)st + part * 32;
        float a0 = 0.f, a1 = 0.f, a2 = 0.f, a3 = 0.f;
#pragma unroll
        for (int j = 0; j < 32; ++j) {
            float4 m = mrow[j], s = s4[j];
            a0 = fmaf(s.x, m.x, a0);
            a1 = fmaf(s.y, m.y, a1);
            a2 = fmaf(s.z, m.z, a2);
            a3 = fmaf(s.w, m.w, a3);
        }
        float acc = (a0 + a1) + (a2 + a3);
        acc += __shfl_xor_sync(0xffffffffu, acc, 1);
        acc += __shfl_xor_sync(0xffffffffu, acc, 2);
        if (part == 0) {
            float s = acc * LIN_SCALE + modb[ci];
            g_s[b * 512 + ci] = s;
            out_s5[b * 512 + ci] = s;
        }
    } else {
        int co = blk - 32, ci = t;
        const float* wp = weight + ((size_t)co * 512 + ci) * 9;
        float w[9], q = 0.f;
#pragma unroll
        for (int k = 0; k < 9; ++k) { w[k] = wp[k]; q = fmaf(w[k], w[k], q); }
        g_wsq[co * 512 + ci] = q;
#pragma unroll
        for (int k = 0; k < 9; ++k)
            g_wt[((size_t)k * COUT + co) * 512 + ci] = __float2half_rn(w[k]);
    }
}

// ---------------- prep2: demod (blocks 0..127) + modxt (blocks 128..2175), 256 thr ----
__global__ void prep2_kernel(const float* __restrict__ x) {
    int blk = blockIdx.x, t = threadIdx.x;
    if (blk < 128) {
        __shared__ float s2[512];
        int b = blk >> 4;
        float sv = g_s[b * 512 + t];
        s2[t] = sv * sv;
        sv = g_s[b * 512 + t + 256];
        s2[t + 256] = sv * sv;
        __syncthreads();
        int co = (blk & 15) * 32 + (t >> 3);
        int part = t & 7;
        const float4* wq = (const float4*)(g_wsq + (size_t)co * 512) + part * 16;
        const float4* s4 = (const float4*)s2 + part * 16;
        float a0 = 0.f, a1 = 0.f, a2 = 0.f, a3 = 0.f;
#pragma unroll
        for (int j = 0; j < 16; ++j) {
            float4 m = wq[j], s = s4[j];
            a0 = fmaf(s.x, m.x, a0);
            a1 = fmaf(s.y, m.y, a1);
            a2 = fmaf(s.z, m.z, a2);
            a3 = fmaf(s.w, m.w, a3);
        }
        float acc = (a0 + a1) + (a2 + a3);
        acc += __shfl_xor_sync(0xffffffffu, acc, 1);
        acc += __shfl_xor_sync(0xffffffffu, acc, 2);
        acc += __shfl_xor_sync(0xffffffffu, acc, 4);
        if (part == 0)
            g_scale[b * 512 + co] = CONV_SCALE * rsqrtf(CONV_SCALE * CONV_SCALE * acc + EPS_);
    } else {
        __shared__ float tt[64][65];
        int idx = blk - 128;               // 0..2047
        int cg  = idx & 3;
        int row = (idx >> 2) & 63;
        int b   = idx >> 8;
        __half* obase = g_xt + ((size_t)b * MPLANE + (size_t)row * WPAD) * CIN;
        if (t < 256) {
            int which = t >> 7, col = (t & 127) + cg * 128;
            obase[(size_t)which * 65 * CIN + col] = __float2half_rn(0.f);
        }
        for (int cc = 0; cc < 2; ++cc) {
            int cic = cg * 2 + cc;
            __syncthreads();
            for (int i = t; i < 4096; i += 256) {
                int ci = i >> 6, w = i & 63;
                float s = g_s[b * 512 + cic * 64 + ci];
                tt[ci][w] = x[((size_t)(b * 512 + cic * 64 + ci)) * HW2 + row * 64 + w] * s;
            }
            __syncthreads();
            for (int i = t; i < 4096; i += 256) {
                int w = i >> 6, ci = i & 63;
                obase[(size_t)(1 + w) * CIN + cic * 64 + ci] = __float2half_rn(tt[ci][w]);
            }
        }
    }
}

// ---------------- conv: tap-resident fp16 GEMM ----------------
// Stage = (kc: 32 ci, kh). A slab (130 rows covers all 3 kw) + 3 kw weight tiles.
// 48 stages, double-buffered, 2 CTAs/SM.
#define BM 128
#define BN 128
#define KSTR 40                      // smem row stride (halves); conflict-free for ldmatrix
#define AROWS 132
#define ASZH (AROWS * KSTR)          // 5280 halves
#define BSZH (3 * 128 * KSTR)        // 15360 halves
#define ABYTES (ASZH * 2)            // 10560
#define STAGEB ((ASZH + BSZH) * 2)   // 41280
#define NST 48
#define SMEM_TOTAL (2 * STAGEB)      // 82560

__global__ __launch_bounds__(256, 2)
void conv_kernel(float* __restrict__ out) {
    extern __shared__ char smch[];

    const int tid = threadIdx.x;
    const int warp = tid >> 5, lane = tid & 31;
    const int wm = warp & 1;
    const int wn = warp >> 1;
    const int gid = lane >> 2;
    const int tig = lane & 3;

    const int co0 = blockIdx.x * BN;
    const int p0 = blockIdx.y * BM;
    const int b = blockIdx.z;

    const __half* Abase = g_xt + (size_t)b * MPLANE * CIN;
    const uint32_t sb = smem_u32(smch);

    const uint32_t a_loff = (((lane & 7) + ((lane >> 3) & 1) * 8) * KSTR + (lane >> 4) * 8) * 2u;
    const uint32_t b_loff = (((lane & 7) + ((lane >> 4) & 1) * 8) * KSTR + ((lane >> 3) & 1) * 8) * 2u;

    float d[4][4][4];
#pragma unroll
    for (int i = 0; i < 4; ++i)
#pragma unroll
        for (int j = 0; j < 4; ++j)
#pragma unroll
            for (int k = 0; k < 4; ++k) d[i][j][k] = 0.f;

    auto load_stage = [&](int s, int buf) {
        const int kc = s / 3, kh = s % 3;
        const uint32_t a0 = sb + (uint32_t)buf * STAGEB;
        const uint32_t b0 = a0 + ABYTES;
        const int prbase = p0 + (kh - 1) * WPAD - 1;
        // A: 130 rows (halo +-1 in kw dir), 528 cp16
#pragma unroll
        for (int i = 0; i < 3; ++i) {
            int idx = tid + i * 256;
            if (idx < 528) {
                int row = idx >> 2, q = idx & 3;
                int pr = prbase + row;
                const __half* src = Abase + (size_t)pr * CIN + kc * 32 + q * 8;
                int sz = ((unsigned)pr < (unsigned)MPLANE) ? 16 : 0;
                cp16(a0 + (uint32_t)(row * KSTR + q * 8) * 2u, src, sz);
            }
        }
        // B: 3 kw taps x 128 co x 4 q = 1536 cp16
#pragma unroll
        for (int i = 0; i < 6; ++i) {
            int idx = tid + i * 256;
            int kw = idx >> 9;
            int r = idx & 511;
            int co = r >> 2, q = r & 3;
            const __half* src = g_wt + ((size_t)(kh * 3 + kw) * COUT + co0 + co) * CIN
                                + kc * 32 + q * 8;
            cp16(b0 + (uint32_t)((kw * 128 + co) * KSTR + q * 8) * 2u, src, 16);
        }
        CP_COMMIT();
    };

    load_stage(0, 0);

    for (int s = 0; s < NST; ++s) {
        CP_WAIT(0);
        __syncthreads();
        if (s + 1 < NST) load_stage(s + 1, (s + 1) & 1);

        const uint32_t a0 = sb + (uint32_t)(s & 1) * STAGEB;
        const uint32_t b0 = a0 + ABYTES;
#pragma unroll
        for (int kw = 0; kw < 3; ++kw) {
#pragma unroll
            for (int ks = 0; ks < 2; ++ks) {
                const int kb = ks * 16;
                uint32_t a[4][4];
#pragma unroll
                for (int fm = 0; fm < 4; ++fm)
                    ldsm4(a[fm], a0 + (uint32_t)((wm * 64 + fm * 16 + kw) * KSTR + kb) * 2u + a_loff);
                uint32_t bf[4][2];
#pragma unroll
                for (int j = 0; j < 2; ++j) {
                    uint32_t r[4];
                    ldsm4(r, b0 + (uint32_t)((kw * 128 + wn * 32 + j * 16) * KSTR + kb) * 2u + b_loff);
                    bf[2 * j][0] = r[0]; bf[2 * j][1] = r[1];
                    bf[2 * j + 1][0] = r[2]; bf[2 * j + 1][1] = r[3];
                }
#pragma unroll
                for (int fm = 0; fm < 4; ++fm)
#pragma unroll
                    for (int fn = 0; fn < 4; ++fn)
                        mma_f16(d[fm][fn], a[fm], bf[fn]);
            }
        }
    }

    // ---- epilogue: transpose through smem, coalesced scaled stores ----
    __syncthreads();
    float* smT = (float*)smch;    // [128 co][132 pix]
#pragma unroll
    for (int fm = 0; fm < 4; ++fm) {
#pragma unroll
        for (int fn = 0; fn < 4; ++fn) {
            int m = wm * 64 + fm * 16 + gid;
            int n = wn * 32 + fn * 8 + tig * 2;
            smT[n * 132 + m]           = d[fm][fn][0];
            smT[(n + 1) * 132 + m]     = d[fm][fn][1];
            smT[n * 132 + m + 8]       = d[fm][fn][2];
            smT[(n + 1) * 132 + m + 8] = d[fm][fn][3];
        }
    }
    __syncthreads();

#pragma unroll 4
    for (int i = 0; i < 64; ++i) {
        int idx = i * 256 + tid;
        int co = idx >> 7, pix = idx & 127;
        int pp = p0 + pix;
        int r = pp / WPAD;
        int w = pp - r * WPAD;
        if (w >= 1 && w <= 64) {
            float sc = g_scale[b * 512 + co0 + co];
            out[((size_t)(b * 512 + co0 + co)) * HW2 + r * 64 + (w - 1)] =
                smT[co * 132 + pix] * sc;
        }
    }
}

// ---------------- launch ----------------
extern "C" void kernel_launch(void* const* d_in, const int* in_sizes, int n_in,
                              void* d_out, int out_size) {
    const float* x      = (const float*)d_in[0];
    const float* style  = (const float*)d_in[1];
    const float* weight = (const float*)d_in[2];
    const float* modw   = (const float*)d_in[3];
    const float* modb   = (const float*)d_in[4];
    float* out = (float*)d_out;
    float* out_s5 = out + (size_t)B_ * COUT * HW2;

    static int smem_set = 0;
    if (!smem_set) {
        cudaFuncSetAttribute(conv_kernel, cudaFuncAttributeMaxDynamicSharedMemorySize,
                             SMEM_TOTAL);
        smem_set = 1;
    }

    prep1_kernel<<<544, 512>>>(style, modw, modb, weight, out_s5);
    prep2_kernel<<<2176, 256>>>(x);

    dim3 grid(COUT / BN, 33, B_);   // 4 x 33 x 8 = 1056 CTAs
    conv_kernel<<<grid, 256, SMEM_TOTAL>>>(out);
}